// round 2
// baseline (speedup 1.0000x reference)
#include <cuda_runtime.h>
#include <cuda_bf16.h>

// Problem constants (fixed by the reference):
//   X:              [4096, 64]  f32   (d_in[0])
//   manifold_ptsX:  [65536, 64] f32   (d_in[1])
//   d_ui_sigma, d_ui_uj_sigma: UNUSED by the reference
//   out:            [4096, 64]  f32  = manifold_ptsX[argmin_j ||x - p_j||^2]
#define NQ     4096
#define MP     65536
#define DIM    64
#define QTILE  128              // queries per CTA == threads per CTA
#define NCHUNK 32               // point chunks (== warp size for the merge kernel)
#define CHUNK  (MP / NCHUNK)    // 2048 points per chunk
#define PTILE  128              // points staged in smem per inner iteration

// Scratch (no allocations allowed -> __device__ globals)
__device__ float g_halfnorm[MP];           // 0.5 * ||p_j||^2
__device__ float g_pscore[NCHUNK * NQ];    // per-chunk best score per query
__device__ int   g_pidx[NCHUNK * NQ];      // per-chunk best index per query

// ---- packed f32x2 helpers (ptxas will NOT auto-fuse; PTX-only per SASS_QUICKREF) ----
static __device__ __forceinline__ unsigned long long f2fma(unsigned long long a,
                                                           unsigned long long b,
                                                           unsigned long long c) {
    unsigned long long d;
    asm("fma.rn.f32x2 %0, %1, %2, %3;" : "=l"(d) : "l"(a), "l"(b), "l"(c));
    return d;
}
static __device__ __forceinline__ unsigned long long f2add(unsigned long long a,
                                                           unsigned long long b) {
    unsigned long long d;
    asm("add.rn.f32x2 %0, %1, %2;" : "=l"(d) : "l"(a), "l"(b));
    return d;
}
static __device__ __forceinline__ float f2hsum(unsigned long long v) {
    float lo, hi;
    asm("mov.b64 {%0, %1}, %2;" : "=f"(lo), "=f"(hi) : "l"(v));
    return lo + hi;
}

// ---- kernel 0: half squared norms of all manifold points ----
__global__ void halfnorm_kernel(const float* __restrict__ P) {
    int j = blockIdx.x * blockDim.x + threadIdx.x;   // exact: MP = 256*256
    const float4* r = (const float4*)(P + (size_t)j * DIM);
    float s = 0.f;
#pragma unroll
    for (int i = 0; i < DIM / 4; i++) {
        float4 v = r[i];
        s += v.x * v.x + v.y * v.y + v.z * v.z + v.w * v.w;
    }
    g_halfnorm[j] = 0.5f * s;
}

// ---- kernel 1: partial argmin over a chunk of points ----
// Grid: (NQ/QTILE, NCHUNK). Each thread owns one query (64 dims in 32 packed-u64 regs).
__global__ void __launch_bounds__(QTILE, 2)
nn_partial_kernel(const float* __restrict__ X, const float* __restrict__ P) {
    __shared__ __align__(16) float s_pts[PTILE * DIM];   // 32 KB
    __shared__ float s_nrm[PTILE];

    const int t     = threadIdx.x;
    const int q     = blockIdx.x * QTILE + t;
    const int pbase = blockIdx.y * CHUNK;

    // Query row -> registers as 32 packed f32x2 values (ulonglong2 = LDG.128)
    unsigned long long xr[DIM / 2];
    {
        const ulonglong2* xg = (const ulonglong2*)(X + (size_t)q * DIM);
#pragma unroll
        for (int i = 0; i < DIM / 4; i++) {
            ulonglong2 v = xg[i];
            xr[2 * i]     = v.x;
            xr[2 * i + 1] = v.y;
        }
    }

    float best = 3.402823466e38f;
    int   bidx = 0;

#pragma unroll 1
    for (int tile = 0; tile < CHUNK; tile += PTILE) {
        // Cooperative, coalesced stage of PTILE points (128 x 64 f32) into smem
        const float4* gsrc = (const float4*)(P + (size_t)(pbase + tile) * DIM);
        float4* sdst = (float4*)s_pts;
#pragma unroll
        for (int i = 0; i < (PTILE * DIM / 4) / QTILE; i++)   // 16 iterations
            sdst[t + i * QTILE] = gsrc[t + i * QTILE];
        s_nrm[t] = g_halfnorm[pbase + tile + t];              // QTILE == PTILE
        __syncthreads();

#pragma unroll 4
        for (int p = 0; p < PTILE; p++) {
            const ulonglong2* pp = (const ulonglong2*)(s_pts + p * DIM);
            unsigned long long a0 = 0ull, a1 = 0ull, a2 = 0ull, a3 = 0ull;
#pragma unroll
            for (int i = 0; i < DIM / 4; i++) {
                ulonglong2 v = pp[i];                          // LDS.128 broadcast
                if (i & 1) {
                    a2 = f2fma(xr[2 * i],     v.x, a2);
                    a3 = f2fma(xr[2 * i + 1], v.y, a3);
                } else {
                    a0 = f2fma(xr[2 * i],     v.x, a0);
                    a1 = f2fma(xr[2 * i + 1], v.y, a1);
                }
            }
            float dot = f2hsum(f2add(f2add(a0, a1), f2add(a2, a3)));
            float sc  = s_nrm[p] - dot;                        // = (d^2 - ||x||^2)/2
            if (sc < best) { best = sc; bidx = pbase + tile + p; }
        }
        __syncthreads();
    }

    g_pscore[blockIdx.y * NQ + q] = best;
    g_pidx[blockIdx.y * NQ + q]   = bidx;
}

// ---- kernel 2: merge NCHUNK partials per query (one warp per query) + gather row ----
__global__ void nn_reduce_kernel(const float* __restrict__ P, float* __restrict__ out) {
    const int warp = threadIdx.x >> 5;
    const int lane = threadIdx.x & 31;
    const int q = blockIdx.x * (blockDim.x >> 5) + warp;

    float s  = g_pscore[lane * NQ + q];    // NCHUNK == 32 == lanes
    int   idx = g_pidx[lane * NQ + q];
#pragma unroll
    for (int off = 16; off; off >>= 1) {
        float os = __shfl_down_sync(0xffffffffu, s, off);
        int   oi = __shfl_down_sync(0xffffffffu, idx, off);
        if (os < s || (os == s && oi < idx)) { s = os; idx = oi; }  // argmin-first tiebreak
    }
    idx = __shfl_sync(0xffffffffu, idx, 0);

    const float2* src = (const float2*)(P + (size_t)idx * DIM);
    float2* dst = (float2*)(out + (size_t)q * DIM);
    dst[lane] = src[lane];                 // 32 lanes x 8B = full 64-float row
}

extern "C" void kernel_launch(void* const* d_in, const int* in_sizes, int n_in,
                              void* d_out, int out_size) {
    const float* X = (const float*)d_in[0];
    const float* P = (const float*)d_in[1];
    float* out = (float*)d_out;

    halfnorm_kernel<<<MP / 256, 256>>>(P);

    dim3 grid(NQ / QTILE, NCHUNK);
    nn_partial_kernel<<<grid, QTILE>>>(X, P);

    nn_reduce_kernel<<<NQ / (256 / 32), 256>>>(P, out);
}

// round 4
// speedup vs baseline: 2.0316x; 2.0316x over previous
#include <cuda_runtime.h>
#include <cuda_bf16.h>
#include <cstdint>

// out[q] = P[argmin_j ||X[q]-P[j]||^2], X:[4096,64]f32, P:[65536,64]f32.
// Screen with warp-level mma.sync bf16 split GEMM (xh*ph + xh*pl + xl*ph,
// err ~3e-5), per-thread top-2 per chunk, exact fp32 rescore of 128 cand/query.
// NOTE: harness ptxas target is sm_103 (no 'a') -> tcgen05 unavailable; use HMMA.
#define NQ 4096
#define MP 65536
#define DIM 64
#define CTAM 128
#define CTAN 128
#define PCHUNK 8
#define PPC (MP / PCHUNK)        // 8192
#define TILES (PPC / CTAN)       // 64
#define NCAND (PCHUNK * 16)      // 128 candidates per query

// ---------------- device scratch ----------------
__device__ __nv_bfloat16 g_Xh[NQ * DIM], g_Xl[NQ * DIM];
__device__ __nv_bfloat16 g_Ph[MP * DIM], g_Pl[MP * DIM];
__device__ float g_hn[MP];                   // 0.5*||p||^2
__device__ int   g_cand[PCHUNK * NQ * 16];   // candidate indices

// ---------------- smem layout (from 1024-aligned base) ----------------
#define A_HI   0                 // 128 x 64 bf16 rows (128B/row), 16KB
#define A_LO   16384
#define B_OFF(buf, hl) (32768 + (buf) * 32768 + (hl) * 16384)
#define NRM_OFF(buf)   (98304 + (buf) * 512)
#define DSMEM_BYTES    (99328 + 1024)

// ---------------- PTX helpers ----------------
static __device__ __forceinline__ uint32_t smem_u32(const void* p) {
    uint32_t a;
    asm("{ .reg .u64 t; cvta.to.shared.u64 t, %1; cvt.u32.u64 %0, t; }" : "=r"(a) : "l"(p));
    return a;
}
#define CP_ASYNC16(dst, src) asm volatile("cp.async.cg.shared.global [%0], [%1], 16;" :: "r"(dst), "l"(src) : "memory")
#define CP_ASYNC4(dst, src)  asm volatile("cp.async.ca.shared.global [%0], [%1], 4;"  :: "r"(dst), "l"(src) : "memory")
#define CP_COMMIT()          asm volatile("cp.async.commit_group;" ::: "memory")
#define CP_WAIT1()           asm volatile("cp.async.wait_group 1;" ::: "memory")

static __device__ __forceinline__ void ldsm_x4(uint32_t a, uint32_t& r0, uint32_t& r1,
                                               uint32_t& r2, uint32_t& r3) {
    asm volatile("ldmatrix.sync.aligned.m8n8.x4.shared.b16 {%0,%1,%2,%3}, [%4];"
                 : "=r"(r0), "=r"(r1), "=r"(r2), "=r"(r3) : "r"(a));
}
static __device__ __forceinline__ void mma_bf16(float* d, const uint32_t* a,
                                                uint32_t b0, uint32_t b1) {
    asm volatile("mma.sync.aligned.m16n8k16.row.col.f32.bf16.bf16.f32 "
                 "{%0,%1,%2,%3}, {%4,%5,%6,%7}, {%8,%9}, {%0,%1,%2,%3};"
                 : "+f"(d[0]), "+f"(d[1]), "+f"(d[2]), "+f"(d[3])
                 : "r"(a[0]), "r"(a[1]), "r"(a[2]), "r"(a[3]), "r"(b0), "r"(b1));
}

// ---------------- preprocessing ----------------
__global__ void convert_P_kernel(const float* __restrict__ P) {
    int i = blockIdx.x * blockDim.x + threadIdx.x;     // over MP*DIM/2 float2
    float2 v = ((const float2*)P)[i];
    __nv_bfloat16 h0 = __float2bfloat16_rn(v.x), h1 = __float2bfloat16_rn(v.y);
    ((__nv_bfloat162*)g_Ph)[i] = __halves2bfloat162(h0, h1);
    ((__nv_bfloat162*)g_Pl)[i] = __halves2bfloat162(
        __float2bfloat16_rn(v.x - __bfloat162float(h0)),
        __float2bfloat16_rn(v.y - __bfloat162float(h1)));
}
__global__ void convert_X_kernel(const float* __restrict__ X) {
    int i = blockIdx.x * blockDim.x + threadIdx.x;     // over NQ*DIM/2 float2
    float2 v = ((const float2*)X)[i];
    __nv_bfloat16 h0 = __float2bfloat16_rn(v.x), h1 = __float2bfloat16_rn(v.y);
    ((__nv_bfloat162*)g_Xh)[i] = __halves2bfloat162(h0, h1);
    ((__nv_bfloat162*)g_Xl)[i] = __halves2bfloat162(
        __float2bfloat16_rn(v.x - __bfloat162float(h0)),
        __float2bfloat16_rn(v.y - __bfloat162float(h1)));
}
__global__ void halfnorm_kernel(const float* __restrict__ P) {
    int j = blockIdx.x * blockDim.x + threadIdx.x;
    const float4* r = (const float4*)(P + (size_t)j * DIM);
    float s = 0.f;
#pragma unroll
    for (int i = 0; i < DIM / 4; i++) {
        float4 v = r[i];
        s += v.x * v.x + v.y * v.y + v.z * v.z + v.w * v.w;
    }
    g_hn[j] = 0.5f * s;
}
__global__ void noop_kernel() {}

// ---------------- screening kernel ----------------
// B tile staging: 16KB region (128 rows x 128B), cp.async 16B x4 per thread.
static __device__ __forceinline__ void stageB(uint32_t sreg, const __nv_bfloat16* src,
                                              int rowbase, int tid) {
#pragma unroll
    for (int i = 0; i < 4; i++) {
        int c = tid + i * 256;
        int row = c >> 3, col = (c & 7) * 16;
        uint32_t d = sreg + row * 128 + (col ^ ((row & 7) << 4));
        const char* s = (const char*)(src + (size_t)(rowbase + row) * DIM) + col;
        CP_ASYNC16(d, s);
    }
}

__global__ void __launch_bounds__(256, 2)
nn_mma_kernel() {
    extern __shared__ char dsm[];
    uint32_t raw = smem_u32(dsm);
    uint32_t sbase = (raw + 1023u) & ~1023u;
    char* sb = dsm + (sbase - raw);

    const int tid = threadIdx.x;
    const int lane = tid & 31, wid = tid >> 5;
    const int warpM = wid >> 1, warpN = wid & 1;
    const int qbase = blockIdx.x * CTAM;
    const int pbase0 = blockIdx.y * PPC;

    // ---- stage A (xh, xl): 128 rows x 128B each, swizzled ----
#pragma unroll
    for (int i = 0; i < 4; i++) {
        int c = tid + i * 256;
        int row = c >> 3, col = (c & 7) * 16;
        uint32_t so = row * 128 + (col ^ ((row & 7) << 4));
        *(uint4*)(sb + A_HI + so) =
            *(const uint4*)((const char*)(g_Xh + (size_t)(qbase + row) * DIM) + col);
        *(uint4*)(sb + A_LO + so) =
            *(const uint4*)((const char*)(g_Xl + (size_t)(qbase + row) * DIM) + col);
    }

    // ---- ldmatrix per-lane address components ----
    // A: row = m0 + (lane&15), col = kbyte + (lane>>4)*16
    const int arow = lane & 15;
    const int acol0 = (lane >> 4) * 16;
    // B: row = n0 + (lane&7) + ((lane>>4)<<3), col = kbyte + ((lane>>3)&1)*16
    const int brow = (lane & 7) + ((lane >> 4) << 3);
    const int bcol0 = ((lane >> 3) & 1) * 16;

    // precomputed A addresses (region-relative) for mt=0,1
    uint32_t aoff[2];
#pragma unroll
    for (int mt = 0; mt < 2; mt++) {
        int r = warpM * 32 + mt * 16 + arow;
        aoff[mt] = r * 128 + (((r & 7) << 4));   // key stored in low bits via XOR at use
    }
    // store row*128 and key separately
    uint32_t arowb[2], akey[2];
#pragma unroll
    for (int mt = 0; mt < 2; mt++) {
        int r = warpM * 32 + mt * 16 + arow;
        arowb[mt] = r * 128; akey[mt] = (r & 7) << 4;
    }
    uint32_t browb[4], bkey[4];
#pragma unroll
    for (int nt2 = 0; nt2 < 4; nt2++) {
        int r = warpN * 64 + nt2 * 16 + brow;
        browb[nt2] = r * 128; bkey[nt2] = (r & 7) << 4;
    }
    (void)aoff;

    // ---- per-query-row top-2 (4 query rows per thread) ----
    float b1[4], b2[4];
    int   i1[4], i2[4];
#pragma unroll
    for (int qi = 0; qi < 4; qi++) { b1[qi] = b2[qi] = 3.402823466e38f; i1[qi] = i2[qi] = 0; }

    // ---- pipeline prologue: stage tile 0 ----
    stageB(sbase + B_OFF(0, 0), g_Ph, pbase0, tid);
    stageB(sbase + B_OFF(0, 1), g_Pl, pbase0, tid);
    if (tid < 128) CP_ASYNC4(sbase + NRM_OFF(0) + tid * 4, g_hn + pbase0 + tid);
    CP_COMMIT();

#pragma unroll 1
    for (int t = 0; t < TILES; t++) {
        const int buf = t & 1;
        if (t + 1 < TILES) {
            const int nb = buf ^ 1, pb = pbase0 + (t + 1) * CTAN;
            stageB(sbase + B_OFF(nb, 0), g_Ph, pb, tid);
            stageB(sbase + B_OFF(nb, 1), g_Pl, pb, tid);
            if (tid < 128) CP_ASYNC4(sbase + NRM_OFF(nb) + tid * 4, g_hn + pb + tid);
        }
        CP_COMMIT();
        CP_WAIT1();
        __syncthreads();

        // ---- compute 128x128 scores: K=192 as 3 segments of 64 ----
        float acc[2][8][4];
#pragma unroll
        for (int mt = 0; mt < 2; mt++)
#pragma unroll
            for (int nt = 0; nt < 8; nt++)
#pragma unroll
                for (int e = 0; e < 4; e++) acc[mt][nt][e] = 0.f;

#pragma unroll
        for (int seg = 0; seg < 3; seg++) {
            const uint32_t Areg = sbase + (seg < 2 ? A_HI : A_LO);
            const uint32_t Breg = sbase + B_OFF(buf, seg == 1 ? 1 : 0);
#pragma unroll
            for (int ks = 0; ks < 4; ks++) {
                const int kb = ks * 32;
                uint32_t a[2][4];
#pragma unroll
                for (int mt = 0; mt < 2; mt++)
                    ldsm_x4(Areg + arowb[mt] + ((kb + acol0) ^ akey[mt]),
                            a[mt][0], a[mt][1], a[mt][2], a[mt][3]);
#pragma unroll
                for (int nt2 = 0; nt2 < 4; nt2++) {
                    uint32_t r0, r1, r2, r3;
                    ldsm_x4(Breg + browb[nt2] + ((kb + bcol0) ^ bkey[nt2]), r0, r1, r2, r3);
                    mma_bf16(acc[0][nt2 * 2],     a[0], r0, r1);
                    mma_bf16(acc[0][nt2 * 2 + 1], a[0], r2, r3);
                    mma_bf16(acc[1][nt2 * 2],     a[1], r0, r1);
                    mma_bf16(acc[1][nt2 * 2 + 1], a[1], r2, r3);
                }
            }
        }

        // ---- epilogue: sc = nrm - dot, per-query-row top-2 with fast min ----
        const float* nrm = (const float*)(sb + NRM_OFF(buf));
        const int colb = warpN * 64 + (lane & 3) * 2;
#pragma unroll
        for (int nt = 0; nt < 8; nt++) {
            float2 nr = *(const float2*)(nrm + colb + nt * 8);
#pragma unroll
            for (int mt = 0; mt < 2; mt++) {
                acc[mt][nt][0] = nr.x - acc[mt][nt][0];
                acc[mt][nt][1] = nr.y - acc[mt][nt][1];
                acc[mt][nt][2] = nr.x - acc[mt][nt][2];
                acc[mt][nt][3] = nr.y - acc[mt][nt][3];
            }
        }
        const int ptile = pbase0 + t * CTAN;
#pragma unroll
        for (int mt = 0; mt < 2; mt++)
#pragma unroll
            for (int e2 = 0; e2 < 2; e2++) {
                const int qi = mt * 2 + e2;
                float m = acc[mt][0][e2 * 2];
#pragma unroll
                for (int nt = 0; nt < 8; nt++) {
                    m = fminf(m, acc[mt][nt][e2 * 2]);
                    m = fminf(m, acc[mt][nt][e2 * 2 + 1]);
                }
                if (m < b2[qi]) {     // rare: rescan 16 with index tracking
#pragma unroll
                    for (int nt = 0; nt < 8; nt++)
#pragma unroll
                        for (int c = 0; c < 2; c++) {
                            float sc = acc[mt][nt][e2 * 2 + c];
                            int gi = ptile + colb + nt * 8 + c;
                            if (sc < b2[qi]) {
                                if (sc < b1[qi]) { b2[qi] = b1[qi]; i2[qi] = i1[qi];
                                                   b1[qi] = sc; i1[qi] = gi; }
                                else             { b2[qi] = sc; i2[qi] = gi; }
                            }
                        }
                }
            }
        __syncthreads();
    }

    // ---- write candidates: 16 per (query, chunk) ----
#pragma unroll
    for (int qi = 0; qi < 4; qi++) {
        const int mt = qi >> 1, e2 = qi & 1;
        const int q = qbase + warpM * 32 + mt * 16 + (lane >> 2) + e2 * 8;
        const int slot = (warpN * 4 + (lane & 3)) * 2;
        const size_t base = ((size_t)blockIdx.y * NQ + q) * 16 + slot;
        g_cand[base] = i1[qi];
        g_cand[base + 1] = i2[qi];
    }
}

// ---------------- exact fp32 rescore (128 candidates/query) + gather ----------------
__global__ void rescore_kernel(const float* __restrict__ X, const float* __restrict__ P,
                               float* __restrict__ out) {
    const int warp = threadIdx.x >> 5, lane = threadIdx.x & 31;
    const int q = blockIdx.x * 8 + warp;

    float xr[DIM];
    {
        const float4* xg = (const float4*)(X + (size_t)q * DIM);
#pragma unroll
        for (int i = 0; i < DIM / 4; i++) {
            float4 v = xg[i];
            xr[4 * i] = v.x; xr[4 * i + 1] = v.y; xr[4 * i + 2] = v.z; xr[4 * i + 3] = v.w;
        }
    }
    float bs = 3.402823466e38f;
    int bi = 0x7fffffff;
#pragma unroll
    for (int j = 0; j < 4; j++) {
        const int c = lane * 4 + j;                  // 0..127
        const int chunk = c >> 4, slot = c & 15;
        const int idx = g_cand[((size_t)chunk * NQ + q) * 16 + slot];
        const float4* pr = (const float4*)(P + (size_t)idx * DIM);
        float dot = 0.f;
#pragma unroll
        for (int i = 0; i < DIM / 4; i++) {
            float4 b = pr[i];
            dot += xr[4 * i] * b.x + xr[4 * i + 1] * b.y
                 + xr[4 * i + 2] * b.z + xr[4 * i + 3] * b.w;
        }
        float sc = g_hn[idx] - dot;
        if (sc < bs || (sc == bs && idx < bi)) { bs = sc; bi = idx; }
    }
#pragma unroll
    for (int off = 16; off; off >>= 1) {
        float os = __shfl_xor_sync(0xffffffffu, bs, off);
        int   oi = __shfl_xor_sync(0xffffffffu, bi, off);
        if (os < bs || (os == bs && oi < bi)) { bs = os; bi = oi; }
    }
    bi = __shfl_sync(0xffffffffu, bi, 0);
    const float2* src = (const float2*)(P + (size_t)bi * DIM);
    ((float2*)(out + (size_t)q * DIM))[lane] = src[lane];
}

// ---------------- launcher ----------------
extern "C" void kernel_launch(void* const* d_in, const int* in_sizes, int n_in,
                              void* d_out, int out_size) {
    const float* X = (const float*)d_in[0];
    const float* P = (const float*)d_in[1];
    float* out = (float*)d_out;

    cudaFuncSetAttribute(nn_mma_kernel, cudaFuncAttributeMaxDynamicSharedMemorySize,
                         DSMEM_BYTES);

    convert_P_kernel<<<MP * DIM / 2 / 256, 256>>>(P);   // 0
    convert_X_kernel<<<NQ * DIM / 2 / 256, 256>>>(X);   // 1
    halfnorm_kernel<<<MP / 256, 256>>>(P);              // 2
    noop_kernel<<<1, 32>>>();                           // 3
    noop_kernel<<<1, 32>>>();                           // 4
    nn_mma_kernel<<<dim3(NQ / CTAM, PCHUNK), 256, DSMEM_BYTES>>>();  // 5 <- ncu target
    rescore_kernel<<<NQ / 8, 256>>>(X, P, out);         // 6
}

// round 9
// speedup vs baseline: 2.2320x; 1.0987x over previous
#include <cuda_runtime.h>
#include <cuda_bf16.h>
#include <cuda_fp8.h>
#include <cstdint>

// out[q] = P[argmin_j ||X[q]-P[j]||^2], X:[4096,64]f32, P:[65536,64]f32.
// Screen: score = 0.5||p||^2 - x.p via bf16 HMMA (xh.ph) + fp8 QMMA cross
// (512xl.p8 + xh8.512pl)/512; noise ~1e-3 on dot. Per-thread top-2 per chunk,
// exact fp32 rescore of 128 cand/query. ptxas target sm_103 (no 'a'): mma.sync only.
#define NQ 4096
#define MP 65536
#define DIM 64
#define CTAM 128
#define CTAN 128
#define PCHUNK 8
#define PPC (MP / PCHUNK)        // 8192
#define TILES (PPC / CTAN)       // 64

// ---------------- device scratch ----------------
__device__ __nv_bfloat16 g_Xh[NQ * DIM];       // bf16(x)
__device__ unsigned char g_X8[NQ * 128];       // row: [e4m3(512*xl) 0..63 | e4m3(x) 64..127]
__device__ __nv_bfloat16 g_Ph[MP * DIM];       // bf16(p)
__device__ unsigned char g_P8[MP * 128];       // row: [e4m3(p) 0..63 | e4m3(512*pl) 64..127]
__device__ float g_hn[MP];                     // 0.5*||p||^2
__device__ int   g_cand[PCHUNK * NQ * 16];

// ---------------- smem layout (from 1024-aligned base) ----------------
#define A_HI   0                      // 128 x 128B (bf16 queries), swizzled
#define A_F8   16384                  // 128 x 128B (fp8 queries)
#define B_OFF(buf, which) (32768 + (buf) * 32768 + (which) * 16384) // which: 0=bf16, 1=fp8
#define NRM_OFF(buf)      (98304 + (buf) * 512)
#define DSMEM_BYTES       (99328 + 1024)

// ---------------- PTX helpers ----------------
static __device__ __forceinline__ uint32_t smem_u32(const void* p) {
    uint32_t a;
    asm("{ .reg .u64 t; cvta.to.shared.u64 t, %1; cvt.u32.u64 %0, t; }" : "=r"(a) : "l"(p));
    return a;
}
#define CP_ASYNC16(dst, src) asm volatile("cp.async.cg.shared.global [%0], [%1], 16;" :: "r"(dst), "l"(src) : "memory")
#define CP_ASYNC4(dst, src)  asm volatile("cp.async.ca.shared.global [%0], [%1], 4;"  :: "r"(dst), "l"(src) : "memory")
#define CP_COMMIT()          asm volatile("cp.async.commit_group;" ::: "memory")
#define CP_WAIT1()           asm volatile("cp.async.wait_group 1;" ::: "memory")

static __device__ __forceinline__ void ldsm_x4(uint32_t a, uint32_t& r0, uint32_t& r1,
                                               uint32_t& r2, uint32_t& r3) {
    asm volatile("ldmatrix.sync.aligned.m8n8.x4.shared.b16 {%0,%1,%2,%3}, [%4];"
                 : "=r"(r0), "=r"(r1), "=r"(r2), "=r"(r3) : "r"(a));
}
static __device__ __forceinline__ void mma_bf16(float* d, const uint32_t* a,
                                                uint32_t b0, uint32_t b1) {
    asm volatile("mma.sync.aligned.m16n8k16.row.col.f32.bf16.bf16.f32 "
                 "{%0,%1,%2,%3}, {%4,%5,%6,%7}, {%8,%9}, {%0,%1,%2,%3};"
                 : "+f"(d[0]), "+f"(d[1]), "+f"(d[2]), "+f"(d[3])
                 : "r"(a[0]), "r"(a[1]), "r"(a[2]), "r"(a[3]), "r"(b0), "r"(b1));
}
static __device__ __forceinline__ void mma_e4m3(float* d, const uint32_t* a,
                                                uint32_t b0, uint32_t b1) {
    asm volatile("mma.sync.aligned.m16n8k32.row.col.f32.e4m3.e4m3.f32 "
                 "{%0,%1,%2,%3}, {%4,%5,%6,%7}, {%8,%9}, {%0,%1,%2,%3};"
                 : "+f"(d[0]), "+f"(d[1]), "+f"(d[2]), "+f"(d[3])
                 : "r"(a[0]), "r"(a[1]), "r"(a[2]), "r"(a[3]), "r"(b0), "r"(b1));
}

static __device__ __forceinline__ uint32_t fp8x4(float a, float b, float c, float d) {
    __nv_fp8x2_storage_t lo = __nv_cvt_float2_to_fp8x2(make_float2(a, b),
                                                       __NV_SATFINITE, __NV_E4M3);
    __nv_fp8x2_storage_t hi = __nv_cvt_float2_to_fp8x2(make_float2(c, d),
                                                       __NV_SATFINITE, __NV_E4M3);
    return (uint32_t)lo | ((uint32_t)hi << 16);
}
// pack two bf16 into a u32 (low = a, high = b)
static __device__ __forceinline__ uint32_t bf2x1(__nv_bfloat16 a, __nv_bfloat16 b) {
    uint16_t ua = __bfloat16_as_ushort(a), ub = __bfloat16_as_ushort(b);
    return (uint32_t)ua | ((uint32_t)ub << 16);
}

// ---------------- preprocessing ----------------
__global__ void convert_P_kernel(const float* __restrict__ P) {
    int i = blockIdx.x * blockDim.x + threadIdx.x;   // MP*16 threads
    int r = i >> 4, k4 = (i & 15) << 2;
    float4 v = *(const float4*)(P + (size_t)r * DIM + k4);
    __nv_bfloat16 h0 = __float2bfloat16_rn(v.x), h1 = __float2bfloat16_rn(v.y);
    __nv_bfloat16 h2 = __float2bfloat16_rn(v.z), h3 = __float2bfloat16_rn(v.w);
    uint2 hh;
    hh.x = bf2x1(h0, h1);
    hh.y = bf2x1(h2, h3);
    *(uint2*)((char*)g_Ph + (size_t)r * 128 + k4 * 2) = hh;
    // fp8 halves: [e4m3(p) | e4m3(512*pl)]
    *(uint32_t*)(g_P8 + (size_t)r * 128 + k4) = fp8x4(v.x, v.y, v.z, v.w);
    float l0 = (v.x - __bfloat162float(h0)) * 512.f;
    float l1 = (v.y - __bfloat162float(h1)) * 512.f;
    float l2 = (v.z - __bfloat162float(h2)) * 512.f;
    float l3 = (v.w - __bfloat162float(h3)) * 512.f;
    *(uint32_t*)(g_P8 + (size_t)r * 128 + 64 + k4) = fp8x4(l0, l1, l2, l3);
}
__global__ void convert_X_kernel(const float* __restrict__ X) {
    int i = blockIdx.x * blockDim.x + threadIdx.x;   // NQ*16 threads
    int r = i >> 4, k4 = (i & 15) << 2;
    float4 v = *(const float4*)(X + (size_t)r * DIM + k4);
    __nv_bfloat16 h0 = __float2bfloat16_rn(v.x), h1 = __float2bfloat16_rn(v.y);
    __nv_bfloat16 h2 = __float2bfloat16_rn(v.z), h3 = __float2bfloat16_rn(v.w);
    uint2 hh;
    hh.x = bf2x1(h0, h1);
    hh.y = bf2x1(h2, h3);
    *(uint2*)((char*)g_Xh + (size_t)r * 128 + k4 * 2) = hh;
    // fp8 pack: [e4m3(512*xl) | e4m3(x)]  (matches B pack so K-dims align)
    float l0 = (v.x - __bfloat162float(h0)) * 512.f;
    float l1 = (v.y - __bfloat162float(h1)) * 512.f;
    float l2 = (v.z - __bfloat162float(h2)) * 512.f;
    float l3 = (v.w - __bfloat162float(h3)) * 512.f;
    *(uint32_t*)(g_X8 + (size_t)r * 128 + k4) = fp8x4(l0, l1, l2, l3);
    *(uint32_t*)(g_X8 + (size_t)r * 128 + 64 + k4) = fp8x4(v.x, v.y, v.z, v.w);
}
__global__ void halfnorm_kernel(const float* __restrict__ P) {
    int j = blockIdx.x * blockDim.x + threadIdx.x;
    const float4* r = (const float4*)(P + (size_t)j * DIM);
    float s = 0.f;
#pragma unroll
    for (int i = 0; i < DIM / 4; i++) {
        float4 v = r[i];
        s += v.x * v.x + v.y * v.y + v.z * v.z + v.w * v.w;
    }
    g_hn[j] = 0.5f * s;
}

// ---------------- screening kernel ----------------
// Stage a 128-row x 128B tile (swizzled) via cp.async; src rows are 128B apart.
static __device__ __forceinline__ void stageB(uint32_t sreg, const char* src, int tid) {
#pragma unroll
    for (int i = 0; i < 4; i++) {
        int c = tid + i * 256;
        int row = c >> 3, col = (c & 7) * 16;
        uint32_t d = sreg + row * 128 + (col ^ ((row & 7) << 4));
        CP_ASYNC16(d, src + (size_t)row * 128 + col);
    }
}

__global__ void __launch_bounds__(256, 2)
nn_mma_kernel() {
    extern __shared__ char dsm[];
    uint32_t raw = smem_u32(dsm);
    uint32_t sbase = (raw + 1023u) & ~1023u;
    char* sb = dsm + (sbase - raw);

    const int tid = threadIdx.x;
    const int lane = tid & 31, wid = tid >> 5;
    const int warpM = wid >> 1, warpN = wid & 1;
    const int qbase = blockIdx.x * CTAM;
    const int pbase0 = blockIdx.y * PPC;

    // ---- stage A (bf16 hi + fp8 pack): 128 rows x 128B each, swizzled ----
#pragma unroll
    for (int i = 0; i < 4; i++) {
        int c = tid + i * 256;
        int row = c >> 3, col = (c & 7) * 16;
        uint32_t so = row * 128 + (col ^ ((row & 7) << 4));
        *(uint4*)(sb + A_HI + so) =
            *(const uint4*)((const char*)g_Xh + (size_t)(qbase + row) * 128 + col);
        *(uint4*)(sb + A_F8 + so) =
            *(const uint4*)((const char*)g_X8 + (size_t)(qbase + row) * 128 + col);
    }

    // ---- ldmatrix per-lane address components (identical pattern bf16/fp8) ----
    const int arow = lane & 15;
    const int acol0 = (lane >> 4) * 16;
    const int brow = (lane & 7) + ((lane >> 4) << 3);
    const int bcol0 = ((lane >> 3) & 1) * 16;

    uint32_t arowb[2], akey[2];
#pragma unroll
    for (int mt = 0; mt < 2; mt++) {
        int r = warpM * 32 + mt * 16 + arow;
        arowb[mt] = r * 128; akey[mt] = (r & 7) << 4;
    }
    uint32_t browb[4], bkey[4];
#pragma unroll
    for (int nt2 = 0; nt2 < 4; nt2++) {
        int r = warpN * 64 + nt2 * 16 + brow;
        browb[nt2] = r * 128; bkey[nt2] = (r & 7) << 4;
    }

    float b1[4], b2[4];
    int   i1[4], i2[4];
#pragma unroll
    for (int qi = 0; qi < 4; qi++) { b1[qi] = b2[qi] = 3.402823466e38f; i1[qi] = i2[qi] = 0; }

    // ---- pipeline prologue ----
    stageB(sbase + B_OFF(0, 0), (const char*)g_Ph + (size_t)pbase0 * 128, tid);
    stageB(sbase + B_OFF(0, 1), (const char*)g_P8 + (size_t)pbase0 * 128, tid);
    if (tid < 128) CP_ASYNC4(sbase + NRM_OFF(0) + tid * 4, g_hn + pbase0 + tid);
    CP_COMMIT();

#pragma unroll 1
    for (int t = 0; t < TILES; t++) {
        const int buf = t & 1;
        if (t + 1 < TILES) {
            const int nb = buf ^ 1, pb = pbase0 + (t + 1) * CTAN;
            stageB(sbase + B_OFF(nb, 0), (const char*)g_Ph + (size_t)pb * 128, tid);
            stageB(sbase + B_OFF(nb, 1), (const char*)g_P8 + (size_t)pb * 128, tid);
            if (tid < 128) CP_ASYNC4(sbase + NRM_OFF(nb) + tid * 4, g_hn + pb + tid);
        }
        CP_COMMIT();
        CP_WAIT1();
        __syncthreads();

        float acc[2][8][4];
#pragma unroll
        for (int mt = 0; mt < 2; mt++)
#pragma unroll
            for (int nt = 0; nt < 8; nt++)
#pragma unroll
                for (int e = 0; e < 4; e++) acc[mt][nt][e] = 0.f;

        // ---- cross terms: fp8 K=128 (4 QMMA k-steps) ----
#pragma unroll
        for (int ks = 0; ks < 4; ks++) {
            const int kb = ks * 32;
            uint32_t a8[2][4];
#pragma unroll
            for (int mt = 0; mt < 2; mt++)
                ldsm_x4(sbase + A_F8 + arowb[mt] + ((kb + acol0) ^ akey[mt]),
                        a8[mt][0], a8[mt][1], a8[mt][2], a8[mt][3]);
#pragma unroll
            for (int nt2 = 0; nt2 < 4; nt2++) {
                uint32_t r0, r1, r2, r3;
                ldsm_x4(sbase + B_OFF(buf, 1) + browb[nt2] + ((kb + bcol0) ^ bkey[nt2]),
                        r0, r1, r2, r3);
                mma_e4m3(acc[0][nt2 * 2],     a8[0], r0, r1);
                mma_e4m3(acc[0][nt2 * 2 + 1], a8[0], r2, r3);
                mma_e4m3(acc[1][nt2 * 2],     a8[1], r0, r1);
                mma_e4m3(acc[1][nt2 * 2 + 1], a8[1], r2, r3);
            }
        }
        // scale cross down by 512
#pragma unroll
        for (int mt = 0; mt < 2; mt++)
#pragma unroll
            for (int nt = 0; nt < 8; nt++)
#pragma unroll
                for (int e = 0; e < 4; e++) acc[mt][nt][e] *= (1.f / 512.f);

        // ---- hi*hi: bf16 K=64 (4 HMMA k-steps) ----
#pragma unroll
        for (int ks = 0; ks < 4; ks++) {
            const int kb = ks * 32;
            uint32_t a[2][4];
#pragma unroll
            for (int mt = 0; mt < 2; mt++)
                ldsm_x4(sbase + A_HI + arowb[mt] + ((kb + acol0) ^ akey[mt]),
                        a[mt][0], a[mt][1], a[mt][2], a[mt][3]);
#pragma unroll
            for (int nt2 = 0; nt2 < 4; nt2++) {
                uint32_t r0, r1, r2, r3;
                ldsm_x4(sbase + B_OFF(buf, 0) + browb[nt2] + ((kb + bcol0) ^ bkey[nt2]),
                        r0, r1, r2, r3);
                mma_bf16(acc[0][nt2 * 2],     a[0], r0, r1);
                mma_bf16(acc[0][nt2 * 2 + 1], a[0], r2, r3);
                mma_bf16(acc[1][nt2 * 2],     a[1], r0, r1);
                mma_bf16(acc[1][nt2 * 2 + 1], a[1], r2, r3);
            }
        }

        // ---- epilogue: sc = nrm - dot, per-query-row top-2 ----
        const float* nrm = (const float*)(sb + NRM_OFF(buf));
        const int colb = warpN * 64 + (lane & 3) * 2;
#pragma unroll
        for (int nt = 0; nt < 8; nt++) {
            float2 nr = *(const float2*)(nrm + colb + nt * 8);
#pragma unroll
            for (int mt = 0; mt < 2; mt++) {
                acc[mt][nt][0] = nr.x - acc[mt][nt][0];
                acc[mt][nt][1] = nr.y - acc[mt][nt][1];
                acc[mt][nt][2] = nr.x - acc[mt][nt][2];
                acc[mt][nt][3] = nr.y - acc[mt][nt][3];
            }
        }
        const int ptile = pbase0 + t * CTAN;
#pragma unroll
        for (int mt = 0; mt < 2; mt++)
#pragma unroll
            for (int e2 = 0; e2 < 2; e2++) {
                const int qi = mt * 2 + e2;
                float m = acc[mt][0][e2 * 2];
#pragma unroll
                for (int nt = 0; nt < 8; nt++) {
                    m = fminf(m, acc[mt][nt][e2 * 2]);
                    m = fminf(m, acc[mt][nt][e2 * 2 + 1]);
                }
                if (m < b2[qi]) {   // rare: rescan 16 with index tracking
#pragma unroll
                    for (int nt = 0; nt < 8; nt++)
#pragma unroll
                        for (int c = 0; c < 2; c++) {
                            float sc = acc[mt][nt][e2 * 2 + c];
                            int gi = ptile + colb + nt * 8 + c;
                            if (sc < b2[qi]) {
                                if (sc < b1[qi]) { b2[qi] = b1[qi]; i2[qi] = i1[qi];
                                                   b1[qi] = sc; i1[qi] = gi; }
                                else             { b2[qi] = sc; i2[qi] = gi; }
                            }
                        }
                }
            }
        __syncthreads();
    }

    // ---- write candidates: 16 per (query, chunk) ----
#pragma unroll
    for (int qi = 0; qi < 4; qi++) {
        const int mt = qi >> 1, e2 = qi & 1;
        const int q = qbase + warpM * 32 + mt * 16 + (lane >> 2) + e2 * 8;
        const int slot = (warpN * 4 + (lane & 3)) * 2;
        const size_t base = ((size_t)blockIdx.y * NQ + q) * 16 + slot;
        g_cand[base] = i1[qi];
        g_cand[base + 1] = i2[qi];
    }
}

// ---------------- exact fp32 rescore (128 candidates/query) + gather ----------------
__global__ void rescore_kernel(const float* __restrict__ X, const float* __restrict__ P,
                               float* __restrict__ out) {
    const int warp = threadIdx.x >> 5, lane = threadIdx.x & 31;
    const int q = blockIdx.x * 8 + warp;

    float xr[DIM];
    {
        const float4* xg = (const float4*)(X + (size_t)q * DIM);
#pragma unroll
        for (int i = 0; i < DIM / 4; i++) {
            float4 v = xg[i];
            xr[4 * i] = v.x; xr[4 * i + 1] = v.y; xr[4 * i + 2] = v.z; xr[4 * i + 3] = v.w;
        }
    }
    float bs = 3.402823466e38f;
    int bi = 0x7fffffff;
#pragma unroll
    for (int j = 0; j < 4; j++) {
        const int c = lane * 4 + j;                  // 0..127
        const int chunk = c >> 4, slot = c & 15;
        const int idx = g_cand[((size_t)chunk * NQ + q) * 16 + slot];
        const float4* pr = (const float4*)(P + (size_t)idx * DIM);
        float dot = 0.f;
#pragma unroll
        for (int i = 0; i < DIM / 4; i++) {
            float4 b = pr[i];
            dot += xr[4 * i] * b.x + xr[4 * i + 1] * b.y
                 + xr[4 * i + 2] * b.z + xr[4 * i + 3] * b.w;
        }
        float sc = g_hn[idx] - dot;
        if (sc < bs || (sc == bs && idx < bi)) { bs = sc; bi = idx; }
    }
#pragma unroll
    for (int off = 16; off; off >>= 1) {
        float os = __shfl_xor_sync(0xffffffffu, bs, off);
        int   oi = __shfl_xor_sync(0xffffffffu, bi, off);
        if (os < bs || (os == bs && oi < bi)) { bs = os; bi = oi; }
    }
    bi = __shfl_sync(0xffffffffu, bi, 0);
    const float2* src = (const float2*)(P + (size_t)bi * DIM);
    ((float2*)(out + (size_t)q * DIM))[lane] = src[lane];
}

// ---------------- launcher ----------------
extern "C" void kernel_launch(void* const* d_in, const int* in_sizes, int n_in,
                              void* d_out, int out_size) {
    const float* X = (const float*)d_in[0];
    const float* P = (const float*)d_in[1];
    float* out = (float*)d_out;

    cudaFuncSetAttribute(nn_mma_kernel, cudaFuncAttributeMaxDynamicSharedMemorySize,
                         DSMEM_BYTES);

    convert_P_kernel<<<MP * 16 / 256, 256>>>(P);    // 0
    convert_X_kernel<<<NQ * 16 / 256, 256>>>(X);    // 1
    halfnorm_kernel<<<MP / 256, 256>>>(P);          // 2
    nn_mma_kernel<<<dim3(NQ / CTAM, PCHUNK), 256, DSMEM_BYTES>>>();  // 3 <- profiled slot
    rescore_kernel<<<NQ / 8, 256>>>(X, P, out);     // 4
}